// round 1
// baseline (speedup 1.0000x reference)
#include <cuda_runtime.h>
#include <math.h>

// Problem constants
#define Bb   4
#define Lt   1024
#define Ct   1024
#define Ht   16
#define Dt   64
#define FFt  4096
#define NTOK (Bb * Lt)            // 4096 tokens
#define SCALE 0.08838834764831843f // (D*2)^-0.5 = 128^-0.5

// ---------------- scratch (static device allocations; allowed) ----------------
static __device__ float g_h   [(size_t)NTOK * Ct];
static __device__ float g_q   [(size_t)NTOK * Ct];
static __device__ float g_k   [(size_t)NTOK * Ct];
static __device__ float g_v   [(size_t)NTOK * Ct];
static __device__ float g_attn[(size_t)NTOK * Ct];
static __device__ float g_proj[(size_t)NTOK * Ct];
static __device__ float g_x1  [(size_t)NTOK * Ct];
static __device__ float g_ff  [(size_t)NTOK * FFt];
static __device__ float g_sc  [(size_t)Bb * Ht * Lt * Lt];   // 256 MB scores/probs

__device__ __forceinline__ float gelu_exact(float x) {
    return 0.5f * x * (1.0f + erff(x * 0.70710678118654752f));
}

// ---------------- generic GEMM: C[M,N] = A[M,K] @ W[N,K]^T + bias (+epilogue) ---
// 128x128 block tile, BK=8, 256 threads, 8x8 per-thread microtile.
enum { EPI_BIAS = 0, EPI_GELU = 1, EPI_RES = 2 };

template <int EPI>
__global__ __launch_bounds__(256) void gemm_kernel(
    const float* __restrict__ A, const float* __restrict__ W,
    const float* __restrict__ bias, const float* __restrict__ res,
    float* __restrict__ C, int M, int N, int K)
{
    __shared__ float As[8][128];
    __shared__ float Bs[8][128];
    const int tid  = threadIdx.x;
    const int tx   = tid & 15;          // 0..15 -> N microtile
    const int ty   = tid >> 4;          // 0..15 -> M microtile
    const int lRow = tid >> 1;          // 0..127
    const int lCol = (tid & 1) << 2;    // 0 or 4

    const float* Ab = A + (size_t)blockIdx.y * 128 * K;
    const float* Wb = W + (size_t)blockIdx.x * 128 * K;

    float acc[8][8];
#pragma unroll
    for (int i = 0; i < 8; i++)
#pragma unroll
        for (int j = 0; j < 8; j++) acc[i][j] = 0.0f;

    for (int k0 = 0; k0 < K; k0 += 8) {
        float4 a4 = *reinterpret_cast<const float4*>(Ab + (size_t)lRow * K + k0 + lCol);
        float4 b4 = *reinterpret_cast<const float4*>(Wb + (size_t)lRow * K + k0 + lCol);
        __syncthreads();
        As[lCol + 0][lRow] = a4.x; As[lCol + 1][lRow] = a4.y;
        As[lCol + 2][lRow] = a4.z; As[lCol + 3][lRow] = a4.w;
        Bs[lCol + 0][lRow] = b4.x; Bs[lCol + 1][lRow] = b4.y;
        Bs[lCol + 2][lRow] = b4.z; Bs[lCol + 3][lRow] = b4.w;
        __syncthreads();
#pragma unroll
        for (int kk = 0; kk < 8; kk++) {
            float4 a0 = *reinterpret_cast<const float4*>(&As[kk][ty * 8]);
            float4 a1 = *reinterpret_cast<const float4*>(&As[kk][ty * 8 + 4]);
            float4 b0 = *reinterpret_cast<const float4*>(&Bs[kk][tx * 8]);
            float4 b1 = *reinterpret_cast<const float4*>(&Bs[kk][tx * 8 + 4]);
            float a[8] = {a0.x, a0.y, a0.z, a0.w, a1.x, a1.y, a1.z, a1.w};
            float b[8] = {b0.x, b0.y, b0.z, b0.w, b1.x, b1.y, b1.z, b1.w};
#pragma unroll
            for (int i = 0; i < 8; i++)
#pragma unroll
                for (int j = 0; j < 8; j++) acc[i][j] = fmaf(a[i], b[j], acc[i][j]);
        }
    }

    const int row0 = blockIdx.y * 128 + ty * 8;
    const int col0 = blockIdx.x * 128 + tx * 8;
#pragma unroll
    for (int i = 0; i < 8; i++) {
        size_t ro = (size_t)(row0 + i) * N + col0;
#pragma unroll
        for (int j = 0; j < 8; j++) {
            float v = acc[i][j] + bias[col0 + j];
            if (EPI == EPI_GELU) v = gelu_exact(v);
            if (EPI == EPI_RES)  v += res[ro + j];
            C[ro + j] = v;
        }
    }
}

// ---------------- attention scores: S = scale*Q@K^T + bias + mask ----------------
// Per (b,h): [L,64] x [L,64]^T -> [L,L]. Same 128x128 tiling, K=64.
__global__ __launch_bounds__(256) void attn_scores_kernel(
    const float* __restrict__ q, const float* __restrict__ k,
    const float* __restrict__ bias, const float* __restrict__ mask,
    float* __restrict__ S)
{
    __shared__ float As[8][128];
    __shared__ float Bs[8][128];
    const int tid  = threadIdx.x;
    const int tx   = tid & 15;
    const int ty   = tid >> 4;
    const int lRow = tid >> 1;
    const int lCol = (tid & 1) << 2;

    const int bh = blockIdx.z;
    const int b  = bh >> 4;
    const int h  = bh & 15;

    const float* Ab = q + (size_t)b * Lt * Ct + h * Dt + (size_t)blockIdx.y * 128 * Ct;
    const float* Bbp = k + (size_t)b * Lt * Ct + h * Dt + (size_t)blockIdx.x * 128 * Ct;

    float acc[8][8];
#pragma unroll
    for (int i = 0; i < 8; i++)
#pragma unroll
        for (int j = 0; j < 8; j++) acc[i][j] = 0.0f;

    for (int k0 = 0; k0 < Dt; k0 += 8) {
        float4 a4 = *reinterpret_cast<const float4*>(Ab  + (size_t)lRow * Ct + k0 + lCol);
        float4 b4 = *reinterpret_cast<const float4*>(Bbp + (size_t)lRow * Ct + k0 + lCol);
        __syncthreads();
        As[lCol + 0][lRow] = a4.x; As[lCol + 1][lRow] = a4.y;
        As[lCol + 2][lRow] = a4.z; As[lCol + 3][lRow] = a4.w;
        Bs[lCol + 0][lRow] = b4.x; Bs[lCol + 1][lRow] = b4.y;
        Bs[lCol + 2][lRow] = b4.z; Bs[lCol + 3][lRow] = b4.w;
        __syncthreads();
#pragma unroll
        for (int kk = 0; kk < 8; kk++) {
            float4 a0 = *reinterpret_cast<const float4*>(&As[kk][ty * 8]);
            float4 a1 = *reinterpret_cast<const float4*>(&As[kk][ty * 8 + 4]);
            float4 b0 = *reinterpret_cast<const float4*>(&Bs[kk][tx * 8]);
            float4 b1 = *reinterpret_cast<const float4*>(&Bs[kk][tx * 8 + 4]);
            float a[8] = {a0.x, a0.y, a0.z, a0.w, a1.x, a1.y, a1.z, a1.w};
            float b[8] = {b0.x, b0.y, b0.z, b0.w, b1.x, b1.y, b1.z, b1.w};
#pragma unroll
            for (int i = 0; i < 8; i++)
#pragma unroll
                for (int j = 0; j < 8; j++) acc[i][j] = fmaf(a[i], b[j], acc[i][j]);
        }
    }

    const size_t sb = (size_t)bh * Lt * Lt;
    const size_t mb = (size_t)b * Lt * Lt;
    const int row0 = blockIdx.y * 128 + ty * 8;
    const int col0 = blockIdx.x * 128 + tx * 8;
#pragma unroll
    for (int i = 0; i < 8; i++) {
        size_t ro = (size_t)(row0 + i) * Lt + col0;
#pragma unroll
        for (int j = 0; j < 8; j++) {
            S[sb + ro + j] = acc[i][j] * SCALE + bias[sb + ro + j] + mask[mb + ro + j];
        }
    }
}

// ---------------- softmax over last dim (L=1024), in-place ----------------
__global__ __launch_bounds__(256) void softmax_kernel(float* __restrict__ S)
{
    const size_t base = (size_t)blockIdx.x * Lt;
    const int tid = threadIdx.x;
    __shared__ float red[32];

    float v[4];
    float mx = -1e30f;
#pragma unroll
    for (int i = 0; i < 4; i++) { v[i] = S[base + tid + i * 256]; mx = fmaxf(mx, v[i]); }
#pragma unroll
    for (int o = 16; o; o >>= 1) mx = fmaxf(mx, __shfl_xor_sync(0xffffffffu, mx, o));
    if ((tid & 31) == 0) red[tid >> 5] = mx;
    __syncthreads();
    if (tid == 0) {
        float m = red[0];
        for (int i = 1; i < 8; i++) m = fmaxf(m, red[i]);
        red[0] = m;
    }
    __syncthreads();
    mx = red[0];

    float s = 0.0f;
#pragma unroll
    for (int i = 0; i < 4; i++) { v[i] = __expf(v[i] - mx); s += v[i]; }
#pragma unroll
    for (int o = 16; o; o >>= 1) s += __shfl_xor_sync(0xffffffffu, s, o);
    __syncthreads();
    if ((tid & 31) == 0) red[tid >> 5] = s;
    __syncthreads();
    if (tid == 0) {
        float t = 0.0f;
        for (int i = 0; i < 8; i++) t += red[i];
        red[0] = t;
    }
    __syncthreads();
    const float inv = 1.0f / red[0];
#pragma unroll
    for (int i = 0; i < 4; i++) S[base + tid + i * 256] = v[i] * inv;
}

// ---------------- attn output: O = P @ V_head, scaled by c_attn[h] -------------
// Per (b,h): [L,L] x [L,64] -> [L,64]. 64x64 block tile, BK=16, 4x4 microtile.
__global__ __launch_bounds__(256) void attn_pv_kernel(
    const float* __restrict__ S, const float* __restrict__ v,
    const float* __restrict__ c_attn, float* __restrict__ out)
{
    __shared__ float Ps[16][64];
    __shared__ float Vs[16][68];
    const int tid = threadIdx.x;
    const int tx = tid & 15;      // 0..15 -> 4 cols each
    const int ty = tid >> 4;      // 0..15 -> 4 rows each
    const int pRow = tid >> 2;          // 0..63
    const int pCol = (tid & 3) << 2;    // 0,4,8,12
    const int vRow = tid >> 4;          // 0..15
    const int vCol = (tid & 15) << 2;   // 0..60

    const int bh = blockIdx.y;
    const int b  = bh >> 4;
    const int h  = bh & 15;

    const float* Pb = S + (size_t)bh * Lt * Lt + (size_t)blockIdx.x * 64 * Lt;
    const float* Vb = v + (size_t)b * Lt * Ct + h * Dt;

    float acc[4][4];
#pragma unroll
    for (int i = 0; i < 4; i++)
#pragma unroll
        for (int j = 0; j < 4; j++) acc[i][j] = 0.0f;

    for (int k0 = 0; k0 < Lt; k0 += 16) {
        float4 p4 = *reinterpret_cast<const float4*>(Pb + (size_t)pRow * Lt + k0 + pCol);
        float4 v4 = *reinterpret_cast<const float4*>(Vb + (size_t)(k0 + vRow) * Ct + vCol);
        __syncthreads();
        Ps[pCol + 0][pRow] = p4.x; Ps[pCol + 1][pRow] = p4.y;
        Ps[pCol + 2][pRow] = p4.z; Ps[pCol + 3][pRow] = p4.w;
        Vs[vRow][vCol + 0] = v4.x; Vs[vRow][vCol + 1] = v4.y;
        Vs[vRow][vCol + 2] = v4.z; Vs[vRow][vCol + 3] = v4.w;
        __syncthreads();
#pragma unroll
        for (int kk = 0; kk < 16; kk++) {
            float a[4] = {Ps[kk][ty * 4 + 0], Ps[kk][ty * 4 + 1],
                          Ps[kk][ty * 4 + 2], Ps[kk][ty * 4 + 3]};
            float bvv[4] = {Vs[kk][tx * 4 + 0], Vs[kk][tx * 4 + 1],
                            Vs[kk][tx * 4 + 2], Vs[kk][tx * 4 + 3]};
#pragma unroll
            for (int i = 0; i < 4; i++)
#pragma unroll
                for (int j = 0; j < 4; j++) acc[i][j] = fmaf(a[i], bvv[j], acc[i][j]);
        }
    }

    const float cs = c_attn[h];
    const int row0 = blockIdx.x * 64 + ty * 4;
    const int col0 = tx * 4;
#pragma unroll
    for (int i = 0; i < 4; i++)
#pragma unroll
        for (int j = 0; j < 4; j++)
            out[((size_t)b * Lt + row0 + i) * Ct + h * Dt + col0 + j] = acc[i][j] * cs;
}

// ---------------- layernorm (optionally + residual) ----------------
template <bool RES>
__global__ __launch_bounds__(256) void ln_kernel(
    const float* __restrict__ in, const float* __restrict__ g, const float* __restrict__ be,
    const float* __restrict__ res, float* __restrict__ out, int cols)
{
    const size_t base = (size_t)blockIdx.x * cols;
    const int tid = threadIdx.x;
    __shared__ float rs[32], rs2[32];

    float s = 0.0f, s2 = 0.0f;
    for (int c = tid; c < cols; c += 256) {
        float x = in[base + c];
        s += x; s2 += x * x;
    }
#pragma unroll
    for (int o = 16; o; o >>= 1) {
        s  += __shfl_xor_sync(0xffffffffu, s,  o);
        s2 += __shfl_xor_sync(0xffffffffu, s2, o);
    }
    if ((tid & 31) == 0) { rs[tid >> 5] = s; rs2[tid >> 5] = s2; }
    __syncthreads();
    if (tid == 0) {
        float a = 0.0f, a2 = 0.0f;
        for (int i = 0; i < 8; i++) { a += rs[i]; a2 += rs2[i]; }
        rs[0] = a; rs2[0] = a2;
    }
    __syncthreads();
    const float icols = 1.0f / (float)cols;
    const float mean = rs[0] * icols;
    const float var  = rs2[0] * icols - mean * mean;
    const float rstd = rsqrtf(var + 1e-5f);

    for (int c = tid; c < cols; c += 256) {
        float x = in[base + c];
        float val = (x - mean) * rstd * g[c] + be[c];
        if (RES) val += res[base + c];
        out[base + c] = val;
    }
}

// ---------------- launch ----------------
extern "C" void kernel_launch(void* const* d_in, const int* in_sizes, int n_in,
                              void* d_out, int out_size)
{
    const float* x       = (const float*)d_in[0];
    const float* ab      = (const float*)d_in[1];
    const float* amask   = (const float*)d_in[2];
    const float* Wq      = (const float*)d_in[3];
    const float* bq      = (const float*)d_in[4];
    const float* Wk      = (const float*)d_in[5];
    const float* bk      = (const float*)d_in[6];
    const float* Wv      = (const float*)d_in[7];
    const float* bv      = (const float*)d_in[8];
    const float* Wo      = (const float*)d_in[9];
    const float* bo      = (const float*)d_in[10];
    const float* c_attn  = (const float*)d_in[11];
    const float* W1      = (const float*)d_in[12];
    const float* b1      = (const float*)d_in[13];
    const float* W2      = (const float*)d_in[14];
    const float* b2      = (const float*)d_in[15];
    const float* ln_g    = (const float*)d_in[16];
    const float* ln_b    = (const float*)d_in[17];
    const float* mln_g   = (const float*)d_in[18];
    const float* mln_b   = (const float*)d_in[19];
    const float* fln_g   = (const float*)d_in[20];
    const float* fln_b   = (const float*)d_in[21];
    const float* fmln_g  = (const float*)d_in[22];
    const float* fmln_b  = (const float*)d_in[23];
    float* out = (float*)d_out;

    float *h_, *q_, *k_, *v_, *attn_, *proj_, *x1_, *ff_, *sc_;
    cudaGetSymbolAddress((void**)&h_,    g_h);
    cudaGetSymbolAddress((void**)&q_,    g_q);
    cudaGetSymbolAddress((void**)&k_,    g_k);
    cudaGetSymbolAddress((void**)&v_,    g_v);
    cudaGetSymbolAddress((void**)&attn_, g_attn);
    cudaGetSymbolAddress((void**)&proj_, g_proj);
    cudaGetSymbolAddress((void**)&x1_,   g_x1);
    cudaGetSymbolAddress((void**)&ff_,   g_ff);
    cudaGetSymbolAddress((void**)&sc_,   g_sc);

    // attention block
    ln_kernel<false><<<NTOK, 256>>>(x, ln_g, ln_b, nullptr, h_, Ct);

    dim3 gq(Ct / 128, NTOK / 128);                 // (8, 32)
    gemm_kernel<EPI_BIAS><<<gq, 256>>>(h_, Wq, bq, nullptr, q_, NTOK, Ct, Ct);
    gemm_kernel<EPI_BIAS><<<gq, 256>>>(h_, Wk, bk, nullptr, k_, NTOK, Ct, Ct);
    gemm_kernel<EPI_BIAS><<<gq, 256>>>(h_, Wv, bv, nullptr, v_, NTOK, Ct, Ct);

    dim3 gs(Lt / 128, Lt / 128, Bb * Ht);           // (8, 8, 64)
    attn_scores_kernel<<<gs, 256>>>(q_, k_, ab, amask, sc_);

    softmax_kernel<<<Bb * Ht * Lt, 256>>>(sc_);     // 65536 rows

    dim3 gp(Lt / 64, Bb * Ht);                      // (16, 64)
    attn_pv_kernel<<<gp, 256>>>(sc_, v_, c_attn, attn_);

    gemm_kernel<EPI_BIAS><<<gq, 256>>>(attn_, Wo, bo, nullptr, proj_, NTOK, Ct, Ct);
    ln_kernel<true><<<NTOK, 256>>>(proj_, mln_g, mln_b, x, x1_, Ct);

    // FFN block
    ln_kernel<false><<<NTOK, 256>>>(x1_, fln_g, fln_b, nullptr, h_, Ct);

    dim3 g1(FFt / 128, NTOK / 128);                 // (32, 32)
    gemm_kernel<EPI_GELU><<<g1, 256>>>(h_, W1, b1, nullptr, ff_, NTOK, FFt, Ct);

    ln_kernel<false><<<NTOK, 256>>>(ff_, fmln_g, fmln_b, nullptr, ff_, FFt); // in-place

    gemm_kernel<EPI_RES><<<gq, 256>>>(ff_, W2, b2, x1_, out, NTOK, Ct, FFt);
}

// round 3
// speedup vs baseline: 2.0274x; 2.0274x over previous
#include <cuda_runtime.h>
#include <cuda_bf16.h>
#include <math.h>
#include <stdint.h>

// Problem constants
#define Bb   4
#define Lt   1024
#define Ct   1024
#define Ht   16
#define Dt   64
#define FFt  4096
#define NTOK (Bb * Lt)
#define SCALE 0.08838834764831843f

// ---------------- scratch (static device allocations; allowed) ----------------
static __device__ float g_q   [(size_t)NTOK * Ct];
static __device__ float g_k   [(size_t)NTOK * Ct];
static __device__ float g_v   [(size_t)NTOK * Ct];
static __device__ float g_attn[(size_t)NTOK * Ct];
static __device__ float g_proj[(size_t)NTOK * Ct];
static __device__ float g_x1  [(size_t)NTOK * Ct];
static __device__ float g_ff  [(size_t)NTOK * FFt];
static __device__ float g_sc  [(size_t)Bb * Ht * Lt * Lt];

// split-bf16 activations (aligned for 16B cp.async)
static __device__ __align__(256) __nv_bfloat16 g_hh[(size_t)NTOK * Ct],  g_hl[(size_t)NTOK * Ct];
static __device__ __align__(256) __nv_bfloat16 g_ah[(size_t)NTOK * Ct],  g_al[(size_t)NTOK * Ct];
static __device__ __align__(256) __nv_bfloat16 g_fh[(size_t)NTOK * FFt], g_fl[(size_t)NTOK * FFt];
// split-bf16 weights
static __device__ __align__(256) __nv_bfloat16 g_wqh[(size_t)Ct * Ct],  g_wql[(size_t)Ct * Ct];
static __device__ __align__(256) __nv_bfloat16 g_wkh[(size_t)Ct * Ct],  g_wkl[(size_t)Ct * Ct];
static __device__ __align__(256) __nv_bfloat16 g_wvh[(size_t)Ct * Ct],  g_wvl[(size_t)Ct * Ct];
static __device__ __align__(256) __nv_bfloat16 g_woh[(size_t)Ct * Ct],  g_wol[(size_t)Ct * Ct];
static __device__ __align__(256) __nv_bfloat16 g_w1h[(size_t)FFt * Ct], g_w1l[(size_t)FFt * Ct];
static __device__ __align__(256) __nv_bfloat16 g_w2h[(size_t)Ct * FFt], g_w2l[(size_t)Ct * FFt];

__device__ __forceinline__ float gelu_exact(float x) {
    return 0.5f * x * (1.0f + erff(x * 0.70710678118654752f));
}

__device__ __forceinline__ uint32_t smem_u32(const void* p) {
    uint32_t a;
    asm("{ .reg .u64 t; cvta.to.shared.u64 t, %1; cvt.u32.u64 %0, t; }" : "=r"(a) : "l"(p));
    return a;
}

// ---------------- HMMA GEMM building blocks (base sm_103 features only) -------
#define LDMX4(d0, d1, d2, d3, addr) \
    asm volatile("ldmatrix.sync.aligned.m8n8.x4.shared.b16 {%0,%1,%2,%3}, [%4];" \
                 : "=r"(d0), "=r"(d1), "=r"(d2), "=r"(d3) : "r"(addr))

#define MMA16816(d, a, b) \
    asm volatile("mma.sync.aligned.m16n8k16.row.col.f32.bf16.bf16.f32 " \
                 "{%0,%1,%2,%3}, {%4,%5,%6,%7}, {%8,%9}, {%0,%1,%2,%3};" \
                 : "+f"((d)[0]), "+f"((d)[1]), "+f"((d)[2]), "+f"((d)[3]) \
                 : "r"((a)[0]), "r"((a)[1]), "r"((a)[2]), "r"((a)[3]), \
                   "r"((b)[0]), "r"((b)[1]))

#define CPASYNC16(saddr, gptr) \
    asm volatile("cp.async.cg.shared.global [%0], [%1], 16;" :: "r"(saddr), "l"(gptr))
#define CPCOMMIT() asm volatile("cp.async.commit_group;")
#define CPWAIT1()  asm volatile("cp.async.wait_group 1;")
#define CPWAIT0()  asm volatile("cp.async.wait_group 0;")

// 128 rows x 32 cols bf16 matrix in smem: 64B rows split into 4x16B segs,
// seg' = s ^ ((r>>1)&3)  -> conflict-free ldmatrix & stores.
__device__ __forceinline__ uint32_t swz(int r, int s) {
    return (uint32_t)(r * 64 + ((s ^ ((r >> 1) & 3)) << 4));
}

// stage layout: Ah @0, Al @8192, Bh @16384, Bl @24576 ; stage = 32768 B
#define STAGE 32768
#define GEMM_SMEM (2 * STAGE)

enum { EPI_BIAS = 0, EPI_GELU = 1, EPI_RES = 2 };

template <int EPI>
__global__ __launch_bounds__(256) void hmma_gemm(
    const __nv_bfloat16* __restrict__ Ah, const __nv_bfloat16* __restrict__ Al,
    const __nv_bfloat16* __restrict__ Bh, const __nv_bfloat16* __restrict__ Bl,
    const float* __restrict__ bias, const float* __restrict__ res,
    float* __restrict__ C, int N, int K)
{
    extern __shared__ __align__(128) char smem[];
    const uint32_t sb = smem_u32(smem);
    const int tid  = threadIdx.x;
    const int lane = tid & 31;
    const int wid  = tid >> 5;
    const int wm   = (wid & 1) * 64;     // warp m-offset (2 warps over M)
    const int wn   = (wid >> 1) * 32;    // warp n-offset (4 warps over N)

    const __nv_bfloat16* gAh = Ah + (size_t)blockIdx.y * 128 * K;
    const __nv_bfloat16* gAl = Al + (size_t)blockIdx.y * 128 * K;
    const __nv_bfloat16* gBh = Bh + (size_t)blockIdx.x * 128 * K;
    const __nv_bfloat16* gBl = Bl + (size_t)blockIdx.x * 128 * K;

    const int nch = K >> 5;

    // per-thread global/smem load mapping: 2 segs of 16B per matrix per chunk
    const int r0 = tid >> 2,          s0 = tid & 3;
    const int r1 = (tid + 256) >> 2;  // s1 == s0
    const uint32_t sw0 = swz(r0, s0);
    const uint32_t sw1 = swz(r1, s0);
    const size_t go0 = (size_t)r0 * K + s0 * 8;
    const size_t go1 = (size_t)r1 * K + s0 * 8;

#define ISSUE(c)                                                              \
    do {                                                                      \
        const uint32_t bs_ = sb + ((c) & 1) * STAGE;                          \
        const size_t kof_ = (size_t)(c) * 32;                                 \
        CPASYNC16(bs_ + 0     + sw0, gAh + go0 + kof_);                       \
        CPASYNC16(bs_ + 0     + sw1, gAh + go1 + kof_);                       \
        CPASYNC16(bs_ + 8192  + sw0, gAl + go0 + kof_);                       \
        CPASYNC16(bs_ + 8192  + sw1, gAl + go1 + kof_);                       \
        CPASYNC16(bs_ + 16384 + sw0, gBh + go0 + kof_);                       \
        CPASYNC16(bs_ + 16384 + sw1, gBh + go1 + kof_);                       \
        CPASYNC16(bs_ + 24576 + sw0, gBl + go0 + kof_);                       \
        CPASYNC16(bs_ + 24576 + sw1, gBl + go1 + kof_);                       \
        CPCOMMIT();                                                           \
    } while (0)

    ISSUE(0);
    ISSUE(1);

    float acc[4][4][4];
#pragma unroll
    for (int i = 0; i < 4; i++)
#pragma unroll
        for (int j = 0; j < 4; j++)
#pragma unroll
            for (int t = 0; t < 4; t++) acc[i][j][t] = 0.0f;

    for (int c = 0; c < nch; c++) {
        if (c < nch - 1) CPWAIT1(); else CPWAIT0();
        __syncthreads();
        const uint32_t base = sb + (c & 1) * STAGE;

#pragma unroll
        for (int ks = 0; ks < 2; ks++) {
            uint32_t ah[4][4], al_[4][4], bh[4][2], bl_[4][2];
            const int ar  = wm + (lane & 15);
            const int as_ = ks * 2 + (lane >> 4);
#pragma unroll
            for (int mi = 0; mi < 4; mi++) {
                uint32_t ad = base + swz(ar + mi * 16, as_);
                LDMX4(ah[mi][0], ah[mi][1], ah[mi][2], ah[mi][3], ad);
                uint32_t ad2 = base + 8192 + swz(ar + mi * 16, as_);
                LDMX4(al_[mi][0], al_[mi][1], al_[mi][2], al_[mi][3], ad2);
            }
            const int br = wn + ((lane >> 4) & 1) * 8 + (lane & 7);
            const int bs2 = ks * 2 + ((lane >> 3) & 1);
#pragma unroll
            for (int np = 0; np < 2; np++) {
                uint32_t bd = base + 16384 + swz(br + np * 16, bs2);
                LDMX4(bh[np * 2][0], bh[np * 2][1], bh[np * 2 + 1][0], bh[np * 2 + 1][1], bd);
                uint32_t bd2 = base + 24576 + swz(br + np * 16, bs2);
                LDMX4(bl_[np * 2][0], bl_[np * 2][1], bl_[np * 2 + 1][0], bl_[np * 2 + 1][1], bd2);
            }
#pragma unroll
            for (int mi = 0; mi < 4; mi++)
#pragma unroll
                for (int nt = 0; nt < 4; nt++) MMA16816(acc[mi][nt], ah[mi], bh[nt]);
#pragma unroll
            for (int mi = 0; mi < 4; mi++)
#pragma unroll
                for (int nt = 0; nt < 4; nt++) MMA16816(acc[mi][nt], ah[mi], bl_[nt]);
#pragma unroll
            for (int mi = 0; mi < 4; mi++)
#pragma unroll
                for (int nt = 0; nt < 4; nt++) MMA16816(acc[mi][nt], al_[mi], bh[nt]);
        }

        __syncthreads();
        if (c + 2 < nch) ISSUE(c + 2);
    }
#undef ISSUE

    // epilogue
    const int rbase = blockIdx.y * 128 + wm + (lane >> 2);
    const int cbase = blockIdx.x * 128 + wn + (lane & 3) * 2;
#pragma unroll
    for (int mi = 0; mi < 4; mi++) {
#pragma unroll
        for (int half = 0; half < 2; half++) {
            const int row = rbase + mi * 16 + half * 8;
            const size_t ro = (size_t)row * N;
#pragma unroll
            for (int nt = 0; nt < 4; nt++) {
                const int col = cbase + nt * 8;
                float v0 = acc[mi][nt][half * 2 + 0] + bias[col];
                float v1 = acc[mi][nt][half * 2 + 1] + bias[col + 1];
                if (EPI == EPI_GELU) { v0 = gelu_exact(v0); v1 = gelu_exact(v1); }
                if (EPI == EPI_RES)  { v0 += res[ro + col]; v1 += res[ro + col + 1]; }
                C[ro + col]     = v0;
                C[ro + col + 1] = v1;
            }
        }
    }
}

// ---------------- fp32 -> split bf16 (hi/lo) ----------------
__global__ __launch_bounds__(256) void split_bf16_kernel(
    const float* __restrict__ s, __nv_bfloat16* __restrict__ hi,
    __nv_bfloat16* __restrict__ lo, int n4)
{
    int i = blockIdx.x * 256 + threadIdx.x;
    if (i >= n4) return;
    float4 v = ((const float4*)s)[i];
    float vv[4] = {v.x, v.y, v.z, v.w};
#pragma unroll
    for (int k = 0; k < 4; k++) {
        __nv_bfloat16 h = __float2bfloat16(vv[k]);
        __nv_bfloat16 l = __float2bfloat16(vv[k] - __bfloat162float(h));
        hi[(size_t)i * 4 + k] = h;
        lo[(size_t)i * 4 + k] = l;
    }
}

// ---------------- layernorm -> split bf16 ----------------
__global__ __launch_bounds__(256) void ln_bf16_kernel(
    const float* __restrict__ in, const float* __restrict__ g, const float* __restrict__ be,
    __nv_bfloat16* __restrict__ hi, __nv_bfloat16* __restrict__ lo, int cols)
{
    const size_t base = (size_t)blockIdx.x * cols;
    const int tid = threadIdx.x;
    __shared__ float rs[32], rs2[32];

    float s = 0.0f, s2 = 0.0f;
    for (int c = tid; c < cols; c += 256) {
        float x = in[base + c];
        s += x; s2 += x * x;
    }
#pragma unroll
    for (int o = 16; o; o >>= 1) {
        s  += __shfl_xor_sync(0xffffffffu, s,  o);
        s2 += __shfl_xor_sync(0xffffffffu, s2, o);
    }
    if ((tid & 31) == 0) { rs[tid >> 5] = s; rs2[tid >> 5] = s2; }
    __syncthreads();
    if (tid == 0) {
        float a = 0.0f, a2 = 0.0f;
        for (int i = 0; i < 8; i++) { a += rs[i]; a2 += rs2[i]; }
        rs[0] = a; rs2[0] = a2;
    }
    __syncthreads();
    const float icols = 1.0f / (float)cols;
    const float mean = rs[0] * icols;
    const float var  = rs2[0] * icols - mean * mean;
    const float rstd = rsqrtf(var + 1e-5f);

    for (int c = tid; c < cols; c += 256) {
        float x = in[base + c];
        float val = (x - mean) * rstd * g[c] + be[c];
        __nv_bfloat16 h = __float2bfloat16(val);
        hi[base + c] = h;
        lo[base + c] = __float2bfloat16(val - __bfloat162float(h));
    }
}

// ---------------- layernorm fp32 (+residual) ----------------
template <bool RES>
__global__ __launch_bounds__(256) void ln_kernel(
    const float* __restrict__ in, const float* __restrict__ g, const float* __restrict__ be,
    const float* __restrict__ res, float* __restrict__ out, int cols)
{
    const size_t base = (size_t)blockIdx.x * cols;
    const int tid = threadIdx.x;
    __shared__ float rs[32], rs2[32];

    float s = 0.0f, s2 = 0.0f;
    for (int c = tid; c < cols; c += 256) {
        float x = in[base + c];
        s += x; s2 += x * x;
    }
#pragma unroll
    for (int o = 16; o; o >>= 1) {
        s  += __shfl_xor_sync(0xffffffffu, s,  o);
        s2 += __shfl_xor_sync(0xffffffffu, s2, o);
    }
    if ((tid & 31) == 0) { rs[tid >> 5] = s; rs2[tid >> 5] = s2; }
    __syncthreads();
    if (tid == 0) {
        float a = 0.0f, a2 = 0.0f;
        for (int i = 0; i < 8; i++) { a += rs[i]; a2 += rs2[i]; }
        rs[0] = a; rs2[0] = a2;
    }
    __syncthreads();
    const float icols = 1.0f / (float)cols;
    const float mean = rs[0] * icols;
    const float var  = rs2[0] * icols - mean * mean;
    const float rstd = rsqrtf(var + 1e-5f);

    for (int c = tid; c < cols; c += 256) {
        float x = in[base + c];
        float val = (x - mean) * rstd * g[c] + be[c];
        if (RES) val += res[base + c];
        out[base + c] = val;
    }
}

// ---------------- attention scores: S = scale*Q@K^T + bias + mask ----------------
__global__ __launch_bounds__(256) void attn_scores_kernel(
    const float* __restrict__ q, const float* __restrict__ k,
    const float* __restrict__ bias, const float* __restrict__ mask,
    float* __restrict__ S)
{
    __shared__ float As[8][128];
    __shared__ float Bs[8][128];
    const int tid  = threadIdx.x;
    const int tx   = tid & 15;
    const int ty   = tid >> 4;
    const int lRow = tid >> 1;
    const int lCol = (tid & 1) << 2;

    const int bh = blockIdx.z;
    const int b  = bh >> 4;
    const int h  = bh & 15;

    const float* Ab  = q + (size_t)b * Lt * Ct + h * Dt + (size_t)blockIdx.y * 128 * Ct;
    const float* Bbp = k + (size_t)b * Lt * Ct + h * Dt + (size_t)blockIdx.x * 128 * Ct;

    float acc[8][8];
#pragma unroll
    for (int i = 0; i < 8; i++)
#pragma unroll
        for (int j = 0; j < 8; j++) acc[i][j] = 0.0f;

    for (int k0 = 0; k0 < Dt; k0 += 8) {
        float4 a4 = *reinterpret_cast<const float4*>(Ab  + (size_t)lRow * Ct + k0 + lCol);
        float4 b4 = *reinterpret_cast<const float4*>(Bbp + (size_t)lRow * Ct + k0 + lCol);
        __syncthreads();
        As[lCol + 0][lRow] = a4.x; As[lCol + 1][lRow] = a4.y;
        As[lCol + 2][lRow] = a4.z; As[lCol + 3][lRow] = a4.w;
        Bs[lCol + 0][lRow] = b4.x; Bs[lCol + 1][lRow] = b4.y;
        Bs[lCol + 2][lRow] = b4.z; Bs[lCol + 3][lRow] = b4.w;
        __syncthreads();
#pragma unroll
        for (int kk = 0; kk < 8; kk++) {
            float4 a0 = *reinterpret_cast<const float4*>(&As[kk][ty * 8]);
            float4 a1 = *reinterpret_cast<const float4*>(&As[kk][ty * 8 + 4]);
            float4 b0 = *reinterpret_cast<const float4*>(&Bs[kk][tx * 8]);
            float4 b1 = *reinterpret_cast<const float4*>(&Bs[kk][tx * 8 + 4]);
            float a[8] = {a0.x, a0.y, a0.z, a0.w, a1.x, a1.y, a1.z, a1.w};
            float bv[8] = {b0.x, b0.y, b0.z, b0.w, b1.x, b1.y, b1.z, b1.w};
#pragma unroll
            for (int i = 0; i < 8; i++)
#pragma unroll
                for (int j = 0; j < 8; j++) acc[i][j] = fmaf(a[i], bv[j], acc[i][j]);
        }
    }

    const size_t sbs = (size_t)bh * Lt * Lt;
    const size_t mb  = (size_t)b * Lt * Lt;
    const int row0 = blockIdx.y * 128 + ty * 8;
    const int col0 = blockIdx.x * 128 + tx * 8;
#pragma unroll
    for (int i = 0; i < 8; i++) {
        size_t ro = (size_t)(row0 + i) * Lt + col0;
#pragma unroll
        for (int j = 0; j < 8; j++)
            S[sbs + ro + j] = acc[i][j] * SCALE + bias[sbs + ro + j] + mask[mb + ro + j];
    }
}

// ---------------- softmax over last dim (L=1024), in-place ----------------
__global__ __launch_bounds__(256) void softmax_kernel(float* __restrict__ S)
{
    const size_t base = (size_t)blockIdx.x * Lt;
    const int tid = threadIdx.x;
    __shared__ float red[32];

    float v[4];
    float mx = -1e30f;
#pragma unroll
    for (int i = 0; i < 4; i++) { v[i] = S[base + tid + i * 256]; mx = fmaxf(mx, v[i]); }
#pragma unroll
    for (int o = 16; o; o >>= 1) mx = fmaxf(mx, __shfl_xor_sync(0xffffffffu, mx, o));
    if ((tid & 31) == 0) red[tid >> 5] = mx;
    __syncthreads();
    if (tid == 0) {
        float m = red[0];
        for (int i = 1; i < 8; i++) m = fmaxf(m, red[i]);
        red[0] = m;
    }
    __syncthreads();
    mx = red[0];

    float s = 0.0f;
#pragma unroll
    for (int i = 0; i < 4; i++) { v[i] = __expf(v[i] - mx); s += v[i]; }
#pragma unroll
    for (int o = 16; o; o >>= 1) s += __shfl_xor_sync(0xffffffffu, s, o);
    __syncthreads();
    if ((tid & 31) == 0) red[tid >> 5] = s;
    __syncthreads();
    if (tid == 0) {
        float t = 0.0f;
        for (int i = 0; i < 8; i++) t += red[i];
        red[0] = t;
    }
    __syncthreads();
    const float inv = 1.0f / red[0];
#pragma unroll
    for (int i = 0; i < 4; i++) S[base + tid + i * 256] = v[i] * inv;
}

// ---------------- attn output: O = P @ V_head, scaled by c_attn[h] -------------
__global__ __launch_bounds__(256) void attn_pv_kernel(
    const float* __restrict__ S, const float* __restrict__ v,
    const float* __restrict__ c_attn, float* __restrict__ out)
{
    __shared__ float Ps[16][64];
    __shared__ float Vs[16][68];
    const int tid = threadIdx.x;
    const int tx = tid & 15;
    const int ty = tid >> 4;
    const int pRow = tid >> 2;
    const int pCol = (tid & 3) << 2;
    const int vRow = tid >> 4;
    const int vCol = (tid & 15) << 2;

    const int bh = blockIdx.y;
    const int b  = bh >> 4;
    const int h  = bh & 15;

    const float* Pb = S + (size_t)bh * Lt * Lt + (size_t)blockIdx.x * 64 * Lt;
    const float* Vb = v + (size_t)b * Lt * Ct + h * Dt;

    float acc[4][4];
#pragma unroll
    for (int i = 0; i < 4; i++)
#pragma unroll
        for (int j = 0; j < 4; j++) acc[i][j] = 0.0f;

    for (int k0 = 0; k0 < Lt; k0 += 16) {
        float4 p4 = *reinterpret_cast<const float4*>(Pb + (size_t)pRow * Lt + k0 + pCol);
        float4 v4 = *reinterpret_cast<const float4*>(Vb + (size_t)(k0 + vRow) * Ct + vCol);
        __syncthreads();
        Ps[pCol + 0][pRow] = p4.x; Ps[pCol + 1][pRow] = p4.y;
        Ps[pCol + 2][pRow] = p4.z; Ps[pCol + 3][pRow] = p4.w;
        Vs[vRow][vCol + 0] = v4.x; Vs[vRow][vCol + 1] = v4.y;
        Vs[vRow][vCol + 2] = v4.z; Vs[vRow][vCol + 3] = v4.w;
        __syncthreads();
#pragma unroll
        for (int kk = 0; kk < 16; kk++) {
            float a[4] = {Ps[kk][ty * 4 + 0], Ps[kk][ty * 4 + 1],
                          Ps[kk][ty * 4 + 2], Ps[kk][ty * 4 + 3]};
            float bvv[4] = {Vs[kk][tx * 4 + 0], Vs[kk][tx * 4 + 1],
                            Vs[kk][tx * 4 + 2], Vs[kk][tx * 4 + 3]};
#pragma unroll
            for (int i = 0; i < 4; i++)
#pragma unroll
                for (int j = 0; j < 4; j++) acc[i][j] = fmaf(a[i], bvv[j], acc[i][j]);
        }
    }

    const float cs = c_attn[h];
    const int row0 = blockIdx.x * 64 + ty * 4;
    const int col0 = tx * 4;
#pragma unroll
    for (int i = 0; i < 4; i++)
#pragma unroll
        for (int j = 0; j < 4; j++)
            out[((size_t)b * Lt + row0 + i) * Ct + h * Dt + col0 + j] = acc[i][j] * cs;
}

// ---------------- launch ----------------
extern "C" void kernel_launch(void* const* d_in, const int* in_sizes, int n_in,
                              void* d_out, int out_size)
{
    const float* x       = (const float*)d_in[0];
    const float* ab      = (const float*)d_in[1];
    const float* amask   = (const float*)d_in[2];
    const float* Wq      = (const float*)d_in[3];
    const float* bq      = (const float*)d_in[4];
    const float* Wk      = (const float*)d_in[5];
    const float* bk      = (const float*)d_in[6];
    const float* Wv      = (const float*)d_in[7];
    const float* bv      = (const float*)d_in[8];
    const float* Wo      = (const float*)d_in[9];
    const float* bo      = (const float*)d_in[10];
    const float* c_attn  = (const float*)d_in[11];
    const float* W1      = (const float*)d_in[12];
    const float* b1      = (const float*)d_in[13];
    const float* W2      = (const float*)d_in[14];
    const float* b2      = (const float*)d_in[15];
    const float* ln_g    = (const float*)d_in[16];
    const float* ln_b    = (const float*)d_in[17];
    const float* mln_g   = (const float*)d_in[18];
    const float* mln_b   = (const float*)d_in[19];
    const float* fln_g   = (const float*)d_in[20];
    const float* fln_b   = (const float*)d_in[21];
    const float* fmln_g  = (const float*)d_in[22];
    const float* fmln_b  = (const float*)d_in[23];
    float* out = (float*)d_out;

    float *q_, *k_, *v_, *attn_, *proj_, *x1_, *ff_, *sc_;
    __nv_bfloat16 *hh, *hl, *ah, *al, *fh, *fl;
    __nv_bfloat16 *wqh, *wql, *wkh, *wkl, *wvh, *wvl, *woh, *wol, *w1h, *w1l, *w2h, *w2l;
    cudaGetSymbolAddress((void**)&q_,    g_q);
    cudaGetSymbolAddress((void**)&k_,    g_k);
    cudaGetSymbolAddress((void**)&v_,    g_v);
    cudaGetSymbolAddress((void**)&attn_, g_attn);
    cudaGetSymbolAddress((void**)&proj_, g_proj);
    cudaGetSymbolAddress((void**)&x1_,   g_x1);
    cudaGetSymbolAddress((void**)&ff_,   g_ff);
    cudaGetSymbolAddress((void**)&sc_,   g_sc);
    cudaGetSymbolAddress((void**)&hh, g_hh);   cudaGetSymbolAddress((void**)&hl, g_hl);
    cudaGetSymbolAddress((void**)&ah, g_ah);   cudaGetSymbolAddress((void**)&al, g_al);
    cudaGetSymbolAddress((void**)&fh, g_fh);   cudaGetSymbolAddress((void**)&fl, g_fl);
    cudaGetSymbolAddress((void**)&wqh, g_wqh); cudaGetSymbolAddress((void**)&wql, g_wql);
    cudaGetSymbolAddress((void**)&wkh, g_wkh); cudaGetSymbolAddress((void**)&wkl, g_wkl);
    cudaGetSymbolAddress((void**)&wvh, g_wvh); cudaGetSymbolAddress((void**)&wvl, g_wvl);
    cudaGetSymbolAddress((void**)&woh, g_woh); cudaGetSymbolAddress((void**)&wol, g_wol);
    cudaGetSymbolAddress((void**)&w1h, g_w1h); cudaGetSymbolAddress((void**)&w1l, g_w1l);
    cudaGetSymbolAddress((void**)&w2h, g_w2h); cudaGetSymbolAddress((void**)&w2l, g_w2l);

    cudaFuncSetAttribute(hmma_gemm<EPI_BIAS>, cudaFuncAttributeMaxDynamicSharedMemorySize, GEMM_SMEM);
    cudaFuncSetAttribute(hmma_gemm<EPI_GELU>, cudaFuncAttributeMaxDynamicSharedMemorySize, GEMM_SMEM);
    cudaFuncSetAttribute(hmma_gemm<EPI_RES>,  cudaFuncAttributeMaxDynamicSharedMemorySize, GEMM_SMEM);

    // weight splits (every call; deterministic)
    const int nCC = Ct * Ct / 4, nFC = FFt * Ct / 4;
    split_bf16_kernel<<<nCC / 256, 256>>>(Wq, wqh, wql, nCC);
    split_bf16_kernel<<<nCC / 256, 256>>>(Wk, wkh, wkl, nCC);
    split_bf16_kernel<<<nCC / 256, 256>>>(Wv, wvh, wvl, nCC);
    split_bf16_kernel<<<nCC / 256, 256>>>(Wo, woh, wol, nCC);
    split_bf16_kernel<<<nFC / 256, 256>>>(W1, w1h, w1l, nFC);
    split_bf16_kernel<<<nFC / 256, 256>>>(W2, w2h, w2l, nFC);

    // ---- attention block ----
    ln_bf16_kernel<<<NTOK, 256>>>(x, ln_g, ln_b, hh, hl, Ct);

    dim3 gq(Ct / 128, NTOK / 128);   // (8, 32)
    hmma_gemm<EPI_BIAS><<<gq, 256, GEMM_SMEM>>>(hh, hl, wqh, wql, bq, nullptr, q_, Ct, Ct);
    hmma_gemm<EPI_BIAS><<<gq, 256, GEMM_SMEM>>>(hh, hl, wkh, wkl, bk, nullptr, k_, Ct, Ct);
    hmma_gemm<EPI_BIAS><<<gq, 256, GEMM_SMEM>>>(hh, hl, wvh, wvl, bv, nullptr, v_, Ct, Ct);

    dim3 gs(Lt / 128, Lt / 128, Bb * Ht);
    attn_scores_kernel<<<gs, 256>>>(q_, k_, ab, amask, sc_);
    softmax_kernel<<<Bb * Ht * Lt, 256>>>(sc_);
    dim3 gp(Lt / 64, Bb * Ht);
    attn_pv_kernel<<<gp, 256>>>(sc_, v_, c_attn, attn_);

    const int nAct = NTOK * Ct / 4;
    split_bf16_kernel<<<nAct / 256, 256>>>(attn_, ah, al, nAct);
    hmma_gemm<EPI_BIAS><<<gq, 256, GEMM_SMEM>>>(ah, al, woh, wol, bo, nullptr, proj_, Ct, Ct);
    ln_kernel<true><<<NTOK, 256>>>(proj_, mln_g, mln_b, x, x1_, Ct);

    // ---- FFN block ----
    ln_bf16_kernel<<<NTOK, 256>>>(x1_, fln_g, fln_b, hh, hl, Ct);

    dim3 g1(FFt / 128, NTOK / 128);  // (32, 32)
    hmma_gemm<EPI_GELU><<<g1, 256, GEMM_SMEM>>>(hh, hl, w1h, w1l, b1, nullptr, ff_, FFt, Ct);

    ln_bf16_kernel<<<NTOK, 256>>>(ff_, fmln_g, fmln_b, fh, fl, FFt);

    hmma_gemm<EPI_RES><<<gq, 256, GEMM_SMEM>>>(fh, fl, w2h, w2l, b2, x1_, out, Ct, FFt);
}